// round 1
// baseline (speedup 1.0000x reference)
#include <cuda_runtime.h>
#include <math_constants.h>
#include <stdint.h>

// Problem shapes (fixed by the reference):
//   inputs    [16,1024,512]  -> flat X [16384, 512]  fp32
//   embedding [8192, 512]                            fp32
// Outputs (concatenated, fp32):
//   quantized_ste [8388608], quantized [8388608], q_loss, e_loss, indices [16384]

#define N_ROWS 16384
#define DIM    512
#define K_CODES 8192
#define NSPLIT 4
#define CODES_PER_SPLIT (K_CODES / NSPLIT)   // 2048
#define NELEM (N_ROWS * DIM)                  // 8388608

// Scratch (device globals: no allocation allowed)
__device__ float  g_xx[N_ROWS];
__device__ float  g_ee[K_CODES];
__device__ float  g_split_d[NSPLIT * N_ROWS];
__device__ int    g_split_k[NSPLIT * N_ROWS];
__device__ double g_partial[N_ROWS];

// ---------------------------------------------------------------------------
// 1) Row norms, replicating a sequential scalar reduction with separately
//    rounded multiply:  acc = fl(acc + fl(v*v)),  j = 0..511 in order.
//    The sub-ulp value of xx determines the fp32 tie-cell placement of the
//    distance comparison, so the *order* here is load-bearing.
// ---------------------------------------------------------------------------
__global__ void norms_kernel(const float* __restrict__ X, const float* __restrict__ E) {
    int i = blockIdx.x * blockDim.x + threadIdx.x;
    if (i < N_ROWS) {
        const float* p = X + (size_t)i * DIM;
        float acc = 0.0f;
        for (int j = 0; j < DIM; ++j) {
            float v = __ldg(p + j);
            acc = __fadd_rn(acc, __fmul_rn(v, v));
        }
        g_xx[i] = acc;
    } else if (i < N_ROWS + K_CODES) {
        int r = i - N_ROWS;
        const float* p = E + (size_t)r * DIM;
        float acc = 0.0f;
        for (int j = 0; j < DIM; ++j) {
            float v = __ldg(p + j);
            acc = __fadd_rn(acc, __fmul_rn(v, v));
        }
        g_ee[r] = acc;
    }
}

// ---------------------------------------------------------------------------
// 2) Fused fp32 GEMM + argmin.
//    Block: 256 threads, tile = 128 rows x 128 codes, k-tile = 16.
//    Each thread: 8x8 accumulators. Epilogue computes
//        d = fl( fl(xx + ee) - fl(2*dot) )
//    exactly (2*dot is exact), and keeps a running (best_d, best_k) per row
//    with FIRST-INDEX tie-breaking at every level (matches jnp.argmin).
//    Dot accumulation order only perturbs at ~1e-9, far inside a tie cell.
// ---------------------------------------------------------------------------
#define TD 16
__global__ __launch_bounds__(256) void gemm_argmin_kernel(
        const float* __restrict__ X, const float* __restrict__ E) {
    __shared__ float As[TD][129];
    __shared__ float Bs[TD][129];
    __shared__ float sd[128][17];
    __shared__ int   sk[128][17];

    int tid = threadIdx.x;
    int tx = tid & 15, ty = tid >> 4;
    int n0 = blockIdx.y * 128;
    int c0 = blockIdx.x * CODES_PER_SPLIT;

    float best_d[8];
    int   best_k[8];
#pragma unroll
    for (int i = 0; i < 8; ++i) { best_d[i] = CUDART_INF_F; best_k[i] = 0x7fffffff; }

    for (int ct = 0; ct < CODES_PER_SPLIT / 128; ++ct) {
        int c1 = c0 + ct * 128;
        float acc[8][8];
#pragma unroll
        for (int i = 0; i < 8; ++i)
#pragma unroll
            for (int j = 0; j < 8; ++j) acc[i][j] = 0.0f;

        for (int dt = 0; dt < DIM / TD; ++dt) {
            int db = dt * TD;
            // Load 128x16 A and B tiles (2048 floats each) as float4s, store
            // transposed into smem [d][row].
#pragma unroll
            for (int q = 0; q < 2; ++q) {
                int f  = tid * 2 + q;     // 0..511
                int r  = f >> 2;          // 0..127
                int d4 = f & 3;           // which float4 within the 16-wide chunk
                float4 va = *reinterpret_cast<const float4*>(
                    X + (size_t)(n0 + r) * DIM + db + d4 * 4);
                As[d4 * 4 + 0][r] = va.x; As[d4 * 4 + 1][r] = va.y;
                As[d4 * 4 + 2][r] = va.z; As[d4 * 4 + 3][r] = va.w;
                float4 vb = *reinterpret_cast<const float4*>(
                    E + (size_t)(c1 + r) * DIM + db + d4 * 4);
                Bs[d4 * 4 + 0][r] = vb.x; Bs[d4 * 4 + 1][r] = vb.y;
                Bs[d4 * 4 + 2][r] = vb.z; Bs[d4 * 4 + 3][r] = vb.w;
            }
            __syncthreads();
#pragma unroll
            for (int kk = 0; kk < TD; ++kk) {
                float a[8], b[8];
#pragma unroll
                for (int i = 0; i < 8; ++i) a[i] = As[kk][ty * 8 + i];
#pragma unroll
                for (int j = 0; j < 8; ++j) b[j] = Bs[kk][tx + 16 * j];
#pragma unroll
                for (int i = 0; i < 8; ++i)
#pragma unroll
                    for (int j = 0; j < 8; ++j)
                        acc[i][j] = __fmaf_rn(a[i], b[j], acc[i][j]);
            }
            __syncthreads();
        }

        // Epilogue: exact reference rounding of the distance.
#pragma unroll
        for (int i = 0; i < 8; ++i) {
            float xxv = g_xx[n0 + ty * 8 + i];
#pragma unroll
            for (int j = 0; j < 8; ++j) {
                int code = c1 + tx + 16 * j;       // ascending in j
                float t = __fadd_rn(xxv, g_ee[code]);
                float d = __fadd_rn(t, __fmul_rn(-2.0f, acc[i][j]));
                if (d < best_d[i] || (d == best_d[i] && code < best_k[i])) {
                    best_d[i] = d; best_k[i] = code;
                }
            }
        }
    }

    // Cross-thread (tx) reduction per row, lowest-index tie-break.
#pragma unroll
    for (int i = 0; i < 8; ++i) {
        sd[ty * 8 + i][tx] = best_d[i];
        sk[ty * 8 + i][tx] = best_k[i];
    }
    __syncthreads();
    if (tid < 128) {
        float bd = sd[tid][0]; int bk = sk[tid][0];
        for (int t = 1; t < 16; ++t) {
            float d = sd[tid][t]; int k = sk[tid][t];
            if (d < bd || (d == bd && k < bk)) { bd = d; bk = k; }
        }
        g_split_d[blockIdx.x * N_ROWS + n0 + tid] = bd;
        g_split_k[blockIdx.x * N_ROWS + n0 + tid] = bk;
    }
}

// ---------------------------------------------------------------------------
// 3) Combine splits -> index, gather embedding, write quantized / STE /
//    indices, and produce per-row double partial sums of (q - x)^2 with the
//    elementwise ops rounded in fp32 exactly as the reference does.
// ---------------------------------------------------------------------------
__global__ __launch_bounds__(128) void output_kernel(
        const float* __restrict__ X, const float* __restrict__ E,
        float* __restrict__ out,
        int off_qste, int off_q, int off_idx, long out_size) {
    int row = blockIdx.x;
    __shared__ int s_idx;
    __shared__ double red[128];

    if (threadIdx.x == 0) {
        float bd = CUDART_INF_F; int bk = 0x7fffffff;
        for (int s = 0; s < NSPLIT; ++s) {           // splits ascending in code
            float d = g_split_d[s * N_ROWS + row];
            int   k = g_split_k[s * N_ROWS + row];
            if (d < bd || (d == bd && k < bk)) { bd = d; bk = k; }
        }
        s_idx = bk;
        if (off_idx >= 0) {
            long p = (long)off_idx + row;
            if (p < out_size) out[p] = (float)bk;
        }
    }
    __syncthreads();
    int idx = s_idx;

    double acc = 0.0;
#pragma unroll
    for (int u = 0; u < 4; ++u) {
        int c = threadIdx.x + u * 128;
        float ev = E[(size_t)idx * DIM + c];
        float xv = X[(size_t)row * DIM + c];
        float diff = __fadd_rn(ev, -xv);             // fl(q - x)
        float qs   = __fadd_rn(xv, diff);            // fl(x + fl(q - x))  (STE)
        long el = (long)row * DIM + c;
        if (off_qste >= 0) { long p = off_qste + el; if (p < out_size) out[p] = qs; }
        if (off_q    >= 0) { long p = off_q    + el; if (p < out_size) out[p] = ev; }
        float sq = __fmul_rn(diff, diff);
        acc += (double)sq;
    }
    red[threadIdx.x] = acc;
    __syncthreads();
    for (int s = 64; s > 0; s >>= 1) {
        if (threadIdx.x < s) red[threadIdx.x] += red[threadIdx.x + s];
        __syncthreads();
    }
    if (threadIdx.x == 0) g_partial[row] = red[0];
}

// ---------------------------------------------------------------------------
// 4) Deterministic loss reduction (fixed-order double tree; q_loss == e_loss
//    numerically). Scalar contributes ~nothing to the global norm, so double
//    accumulation is safely within tolerance of the fp32 tree.
// ---------------------------------------------------------------------------
__global__ __launch_bounds__(512) void loss_kernel(
        float* __restrict__ out, int off_ql, int off_el, long out_size) {
    __shared__ double red[512];
    double a = 0.0;
    int base = threadIdx.x * 32;
    for (int j = 0; j < 32; ++j) a += g_partial[base + j];
    red[threadIdx.x] = a;
    __syncthreads();
    for (int s = 256; s > 0; s >>= 1) {
        if (threadIdx.x < s) red[threadIdx.x] += red[threadIdx.x + s];
        __syncthreads();
    }
    if (threadIdx.x == 0) {
        float l = (float)(red[0] / (double)NELEM);
        if (off_ql >= 0 && off_ql < out_size) out[off_ql] = l;
        if (off_el >= 0 && off_el < out_size) out[off_el] = l;
    }
}

// ---------------------------------------------------------------------------
extern "C" void kernel_launch(void* const* d_in, const int* in_sizes, int n_in,
                              void* d_out, int out_size) {
    const float* X = (const float*)d_in[0];
    const float* E = (const float*)d_in[1];
    float* out = (float*)d_out;

    // Output layout deduced from out_size (tuple concatenation):
    // [qste(8388608), q(8388608), q_loss, e_loss, indices(16384)]
    int off_qste = -1, off_q = -1, off_ql = -1, off_el = -1, off_idx = -1;
    const int NE = NELEM;
    if (out_size >= 2 * NE + 2 + N_ROWS) {
        off_qste = 0; off_q = NE; off_ql = 2 * NE; off_el = 2 * NE + 1; off_idx = 2 * NE + 2;
    } else if (out_size == NE)          { off_qste = 0; }
    else if (out_size == 2 * NE)        { off_qste = 0; off_q = NE; }
    else if (out_size == 2 * NE + 2)    { off_qste = 0; off_q = NE; off_ql = 2 * NE; off_el = 2 * NE + 1; }
    else if (out_size == N_ROWS)        { off_idx = 0; }
    else { // unknown: write in canonical order, bounds-guarded
        off_qste = 0; off_q = NE; off_ql = 2 * NE; off_el = 2 * NE + 1; off_idx = 2 * NE + 2;
    }
    long osz = (long)out_size;

    norms_kernel<<<(N_ROWS + K_CODES + 255) / 256, 256>>>(X, E);

    dim3 grid(NSPLIT, N_ROWS / 128);
    gemm_argmin_kernel<<<grid, 256>>>(X, E);

    output_kernel<<<N_ROWS, 128>>>(X, E, out, off_qste, off_q, off_idx, osz);
    loss_kernel<<<1, 512>>>(out, off_ql, off_el, osz);
}

// round 2
// speedup vs baseline: 3.7371x; 3.7371x over previous
#include <cuda_runtime.h>
#include <math_constants.h>
#include <stdint.h>

// Shapes: X [16384, 512] fp32, E [8192, 512] fp32.
// Out: [qste 8388608, q 8388608, q_loss, e_loss, indices 16384] fp32.

#define N_ROWS 16384
#define DIM    512
#define K_CODES 8192
#define NELEM (N_ROWS * DIM)
#define CAND_CAP 256
#define MARGIN 1.2e-3f

// Scratch (device globals; no allocation allowed)
__device__ float  g_xx[N_ROWS];
__device__ float  g_ee[K_CODES];
__device__ int    g_cnt[N_ROWS];
__device__ uint2  g_cand[N_ROWS * CAND_CAP];   // (d_approx bits, col)
__device__ int    g_idx[N_ROWS];
__device__ double g_partial[N_ROWS];

// ---------------------------------------------------------------------------
// 1) Row norms, sequential order (load-bearing for the fp32 tie cells),
//    plus zeroing the candidate counters for this launch.
// ---------------------------------------------------------------------------
__global__ void norms_kernel(const float* __restrict__ X, const float* __restrict__ E) {
    int i = blockIdx.x * blockDim.x + threadIdx.x;
    if (i < N_ROWS) {
        const float* p = X + (size_t)i * DIM;
        float acc = 0.0f;
        for (int j = 0; j < DIM; ++j) {
            float v = __ldg(p + j);
            acc = __fadd_rn(acc, __fmul_rn(v, v));
        }
        g_xx[i] = acc;
        g_cnt[i] = 0;
    } else if (i < N_ROWS + K_CODES) {
        int r = i - N_ROWS;
        const float* p = E + (size_t)r * DIM;
        float acc = 0.0f;
        for (int j = 0; j < DIM; ++j) {
            float v = __ldg(p + j);
            acc = __fadd_rn(acc, __fmul_rn(v, v));
        }
        g_ee[r] = acc;
    }
}

// ---------------------------------------------------------------------------
// 2) TF32 tensor-core GEMM + per-block min + margin-based candidate push.
//    Block tile 128x128, k-chunk 32, 8 warps (2 m x 4 n), warp tile 64x32,
//    mma.sync.m16n8k8 tf32. Approx distances only; exactness restored by
//    the refine pass.
// ---------------------------------------------------------------------------
#define BM 128
#define BN 128
#define BK 32
#define SA 36   // smem row stride in words: conflict-free STS.128 and frag LDS

__device__ __forceinline__ uint32_t f2tf32(float v) {
    uint32_t r;
    asm("cvt.rna.tf32.f32 %0, %1;" : "=r"(r) : "f"(v));
    return r;
}

__device__ __forceinline__ void mma8(float* c, const uint32_t* a, const uint32_t* b) {
    asm volatile(
        "mma.sync.aligned.m16n8k8.row.col.f32.tf32.tf32.f32 "
        "{%0,%1,%2,%3}, {%4,%5,%6,%7}, {%8,%9}, {%0,%1,%2,%3};"
        : "+f"(c[0]), "+f"(c[1]), "+f"(c[2]), "+f"(c[3])
        : "r"(a[0]), "r"(a[1]), "r"(a[2]), "r"(a[3]), "r"(b[0]), "r"(b[1]));
}

__global__ __launch_bounds__(256, 2) void gemm_select_kernel(
        const float* __restrict__ X, const float* __restrict__ E) {
    __shared__ uint32_t As[BM * SA];
    __shared__ uint32_t Bs[BN * SA];
    __shared__ int   s_min[BM];
    __shared__ float s_xx[BM];
    __shared__ float s_ee[BN];

    int tid = threadIdx.x;
    int lane = tid & 31, wid = tid >> 5;
    int wm = wid >> 2, wn = wid & 3;       // 2 x 4 warp grid
    int n0 = blockIdx.y * BM;
    int c0 = blockIdx.x * BN;

    if (tid < BM) { s_min[tid] = 0x7f7fffff; s_xx[tid] = g_xx[n0 + tid]; }
    if (tid < BN) s_ee[tid] = g_ee[c0 + tid];

    float acc[4][4][4];
#pragma unroll
    for (int mt = 0; mt < 4; ++mt)
#pragma unroll
        for (int nt = 0; nt < 4; ++nt)
#pragma unroll
            for (int h = 0; h < 4; ++h) acc[mt][nt][h] = 0.0f;

    int lrow = tid >> 3;   // 0..31
    int lk4  = tid & 7;    // 0..7 -> k offset lk4*4

    for (int kt = 0; kt < DIM; kt += BK) {
        __syncthreads();
#pragma unroll
        for (int i = 0; i < 4; ++i) {
            int row = lrow + 32 * i;
            float4 va = *reinterpret_cast<const float4*>(
                X + (size_t)(n0 + row) * DIM + kt + lk4 * 4);
            uint4 ua;
            ua.x = f2tf32(va.x); ua.y = f2tf32(va.y);
            ua.z = f2tf32(va.z); ua.w = f2tf32(va.w);
            *reinterpret_cast<uint4*>(As + row * SA + lk4 * 4) = ua;
            float4 vb = *reinterpret_cast<const float4*>(
                E + (size_t)(c0 + row) * DIM + kt + lk4 * 4);
            uint4 ub;
            ub.x = f2tf32(vb.x); ub.y = f2tf32(vb.y);
            ub.z = f2tf32(vb.z); ub.w = f2tf32(vb.w);
            *reinterpret_cast<uint4*>(Bs + row * SA + lk4 * 4) = ub;
        }
        __syncthreads();
#pragma unroll
        for (int k8 = 0; k8 < BK; k8 += 8) {
            uint32_t af[4][4], bf[4][2];
            int kb = k8 + (lane & 3);
#pragma unroll
            for (int mt = 0; mt < 4; ++mt) {
                int r = wm * 64 + mt * 16 + (lane >> 2);
                af[mt][0] = As[r * SA + kb];
                af[mt][1] = As[(r + 8) * SA + kb];
                af[mt][2] = As[r * SA + kb + 4];
                af[mt][3] = As[(r + 8) * SA + kb + 4];
            }
#pragma unroll
            for (int nt = 0; nt < 4; ++nt) {
                int c = wn * 32 + nt * 8 + (lane >> 2);
                bf[nt][0] = Bs[c * SA + kb];
                bf[nt][1] = Bs[c * SA + kb + 4];
            }
#pragma unroll
            for (int mt = 0; mt < 4; ++mt)
#pragma unroll
                for (int nt = 0; nt < 4; ++nt)
                    mma8(acc[mt][nt], af[mt], bf[nt]);
        }
    }

    // Epilogue: approx distances, per-row block min, margin push.
#pragma unroll
    for (int mt = 0; mt < 4; ++mt) {
#pragma unroll
        for (int rr = 0; rr < 2; ++rr) {
            int rowb = wm * 64 + mt * 16 + (lane >> 2) + 8 * rr;
            float xxv = s_xx[rowb];
            float dmin_t = CUDART_INF_F;
#pragma unroll
            for (int nt = 0; nt < 4; ++nt) {
#pragma unroll
                for (int cc = 0; cc < 2; ++cc) {
                    int h = rr * 2 + cc;
                    int colb = wn * 32 + nt * 8 + 2 * (lane & 3) + cc;
                    float d = (xxv + s_ee[colb]) - 2.0f * acc[mt][nt][h];
                    acc[mt][nt][h] = d;
                    dmin_t = fminf(dmin_t, d);
                }
            }
            atomicMin(&s_min[rowb], __float_as_int(dmin_t));  // positive floats
        }
    }
    __syncthreads();
#pragma unroll
    for (int mt = 0; mt < 4; ++mt) {
#pragma unroll
        for (int rr = 0; rr < 2; ++rr) {
            int rowb = wm * 64 + mt * 16 + (lane >> 2) + 8 * rr;
            float thr = __int_as_float(s_min[rowb]) + MARGIN;
#pragma unroll
            for (int nt = 0; nt < 4; ++nt) {
#pragma unroll
                for (int cc = 0; cc < 2; ++cc) {
                    int h = rr * 2 + cc;
                    float d = acc[mt][nt][h];
                    if (d <= thr) {
                        int gr = n0 + rowb;
                        int gc = c0 + wn * 32 + nt * 8 + 2 * (lane & 3) + cc;
                        int slot = atomicAdd(&g_cnt[gr], 1);
                        if (slot < CAND_CAP)
                            g_cand[gr * CAND_CAP + slot] =
                                make_uint2(__float_as_uint(d), (unsigned)gc);
                    }
                }
            }
        }
    }
}

// ---------------------------------------------------------------------------
// 3) Refine: per row, global approx min over pushed candidates (every block
//    pushed its min, so the global approx min is present), filter to margin,
//    exact fp32 re-evaluation with reference rounding + lowest-index ties.
// ---------------------------------------------------------------------------
__global__ __launch_bounds__(256) void refine_kernel(
        const float* __restrict__ X, const float* __restrict__ E) {
    int row = blockIdx.x;
    int tid = threadIdx.x;
    int lane = tid & 31, wid = tid >> 5;

    __shared__ float s_red[8];
    __shared__ float s_dot[8];
    __shared__ int   s_fc[64];
    __shared__ int   s_m;
    __shared__ float s_bd;
    __shared__ int   s_bk;

    int n = g_cnt[row];
    if (n > CAND_CAP) n = CAND_CAP;

    float d = CUDART_INF_F;
    int   c = 0x7fffffff;
    if (tid < n) {
        uint2 u = g_cand[row * CAND_CAP + tid];
        d = __uint_as_float(u.x);
        c = (int)u.y;
    }
    // block min of approx d
    float m = d;
#pragma unroll
    for (int o = 16; o > 0; o >>= 1) m = fminf(m, __shfl_xor_sync(0xffffffffu, m, o));
    if (lane == 0) s_red[wid] = m;
    if (tid == 0) s_m = 0;
    __syncthreads();
    if (tid == 0) {
        float mm = s_red[0];
#pragma unroll
        for (int w = 1; w < 8; ++w) mm = fminf(mm, s_red[w]);
        s_red[0] = mm;
    }
    __syncthreads();
    float thr = s_red[0] + MARGIN;
    if (tid < n && d <= thr) {
        int s = atomicAdd(&s_m, 1);
        if (s < 64) s_fc[s] = c;
    }
    __syncthreads();
    int m2 = s_m < 64 ? s_m : 64;

    const float* xr = X + (size_t)row * DIM;
    for (int j = 0; j < m2; ++j) {
        int cc = s_fc[j];
        const float* er = E + (size_t)cc * DIM;
        float a = __fmaf_rn(xr[tid], er[tid], 0.0f);
        a = __fmaf_rn(xr[tid + 256], er[tid + 256], a);
#pragma unroll
        for (int o = 16; o > 0; o >>= 1) a += __shfl_xor_sync(0xffffffffu, a, o);
        if (lane == 0) s_dot[wid] = a;
        __syncthreads();
        if (tid == 0) {
            float dot = s_dot[0];
#pragma unroll
            for (int w = 1; w < 8; ++w) dot += s_dot[w];
            float de = __fadd_rn(__fadd_rn(g_xx[row], g_ee[cc]),
                                 __fmul_rn(-2.0f, dot));
            if (j == 0) { s_bd = de; s_bk = cc; }
            else if (de < s_bd || (de == s_bd && cc < s_bk)) { s_bd = de; s_bk = cc; }
        }
        __syncthreads();
    }
    if (tid == 0) g_idx[row] = s_bk;
}

// ---------------------------------------------------------------------------
// 4) Outputs: gather + STE + per-row double partials of (q-x)^2.
// ---------------------------------------------------------------------------
__global__ __launch_bounds__(128) void output_kernel(
        const float* __restrict__ X, const float* __restrict__ E,
        float* __restrict__ out,
        int off_qste, int off_q, int off_idx, long out_size) {
    int row = blockIdx.x;
    __shared__ double red[128];
    int idx = g_idx[row];

    if (threadIdx.x == 0 && off_idx >= 0) {
        long p = (long)off_idx + row;
        if (p < out_size) out[p] = (float)idx;
    }

    double acc = 0.0;
#pragma unroll
    for (int u = 0; u < 4; ++u) {
        int cdim = threadIdx.x + u * 128;
        float ev = E[(size_t)idx * DIM + cdim];
        float xv = X[(size_t)row * DIM + cdim];
        float diff = __fadd_rn(ev, -xv);
        float qs   = __fadd_rn(xv, diff);
        long el = (long)row * DIM + cdim;
        if (off_qste >= 0) { long p = off_qste + el; if (p < out_size) out[p] = qs; }
        if (off_q    >= 0) { long p = off_q    + el; if (p < out_size) out[p] = ev; }
        acc += (double)__fmul_rn(diff, diff);
    }
    red[threadIdx.x] = acc;
    __syncthreads();
    for (int s = 64; s > 0; s >>= 1) {
        if (threadIdx.x < s) red[threadIdx.x] += red[threadIdx.x + s];
        __syncthreads();
    }
    if (threadIdx.x == 0) g_partial[row] = red[0];
}

__global__ __launch_bounds__(512) void loss_kernel(
        float* __restrict__ out, int off_ql, int off_el, long out_size) {
    __shared__ double red[512];
    double a = 0.0;
    int base = threadIdx.x * 32;
    for (int j = 0; j < 32; ++j) a += g_partial[base + j];
    red[threadIdx.x] = a;
    __syncthreads();
    for (int s = 256; s > 0; s >>= 1) {
        if (threadIdx.x < s) red[threadIdx.x] += red[threadIdx.x + s];
        __syncthreads();
    }
    if (threadIdx.x == 0) {
        float l = (float)(red[0] / (double)NELEM);
        if (off_ql >= 0 && off_ql < out_size) out[off_ql] = l;
        if (off_el >= 0 && off_el < out_size) out[off_el] = l;
    }
}

// ---------------------------------------------------------------------------
extern "C" void kernel_launch(void* const* d_in, const int* in_sizes, int n_in,
                              void* d_out, int out_size) {
    const float* X = (const float*)d_in[0];
    const float* E = (const float*)d_in[1];
    float* out = (float*)d_out;

    int off_qste = -1, off_q = -1, off_ql = -1, off_el = -1, off_idx = -1;
    const int NE = NELEM;
    if (out_size >= 2 * NE + 2 + N_ROWS) {
        off_qste = 0; off_q = NE; off_ql = 2 * NE; off_el = 2 * NE + 1; off_idx = 2 * NE + 2;
    } else if (out_size == NE)          { off_qste = 0; }
    else if (out_size == 2 * NE)        { off_qste = 0; off_q = NE; }
    else if (out_size == 2 * NE + 2)    { off_qste = 0; off_q = NE; off_ql = 2 * NE; off_el = 2 * NE + 1; }
    else if (out_size == N_ROWS)        { off_idx = 0; }
    else {
        off_qste = 0; off_q = NE; off_ql = 2 * NE; off_el = 2 * NE + 1; off_idx = 2 * NE + 2;
    }
    long osz = (long)out_size;

    norms_kernel<<<(N_ROWS + K_CODES + 255) / 256, 256>>>(X, E);

    dim3 grid(K_CODES / BN, N_ROWS / BM);   // 64 x 128
    gemm_select_kernel<<<grid, 256>>>(X, E);

    refine_kernel<<<N_ROWS, 256>>>(X, E);
    output_kernel<<<N_ROWS, 128>>>(X, E, out, off_qste, off_q, off_idx, osz);
    loss_kernel<<<1, 512>>>(out, off_ql, off_el, osz);
}